// round 13
// baseline (speedup 1.0000x reference)
#include <cuda_runtime.h>

#define TPB   256
#define OPT   2                 // outputs per thread per iteration
#define NSM   148
#define CPS   4                 // CTAs per SM (pinned via launch_bounds)
#define GRID  (NSM * CPS)       // single wave: every SM holds exactly 4 CTAs

typedef unsigned long long u64;

// ---- packed f32x2 helpers (sm_103a FFMA2 path, PTX-only) ----
__device__ __forceinline__ u64 pack2(float lo, float hi) {
    u64 r; asm("mov.b64 %0, {%1, %2};" : "=l"(r) : "f"(lo), "f"(hi)); return r;
}
__device__ __forceinline__ void unpack2(u64 v, float& lo, float& hi) {
    asm("mov.b64 {%0, %1}, %2;" : "=f"(lo), "=f"(hi) : "l"(v));
}
__device__ __forceinline__ u64 fma2(u64 a, u64 b, u64 c) {
    u64 d; asm("fma.rn.f32x2 %0, %1, %2, %3;" : "=l"(d) : "l"(a), "l"(b), "l"(c)); return d;
}

// GMP DPD, real-part output:
//   Re(y[n]) = sum_{d=0..3} ( a[n-d]*wr_d(n) - b[n-d]*wi_d(n) )
//   w_d(n)   = c(1,d) + sum_{off=-2..2} P_{d,off}(r2[n-d+off])
//   P(s)     = s*(c2 + s*(c4 + s*c6))        (Horner in s = |x|^2)
// Even powers only -> no sqrt; x zero-padded outside [0,N) (matches reference
// delay/lag/lead concats). Horner eliminates the r4/r6 register arrays while
// keeping the FFMA2 count identical (3 per (d,off) triple).
//
// Coefficient column order (reference basis):
//   [0:16)  main : order {1,3,5,7} x delay {0..3}
//   [16:40) lag  : order {3,5,7} x lag  {1,2} x delay {0..3}
//   [40:64) lead : order {3,5,7} x lead {1,2} x delay {0..3}
// (c2,c4,c6) column triples per (d, off):
//   off= 0: ( 4+d,  8+d, 12+d)   off=-1: (16+d, 24+d, 32+d)
//   off=-2: (20+d, 28+d, 36+d)   off=+1: (40+d, 48+d, 56+d)
//   off=+2: (44+d, 52+d, 60+d)
__global__ __launch_bounds__(TPB, CPS)
void dpd_kernel(const float* __restrict__ xr, const float* __restrict__ xi,
                const float* __restrict__ cr, const float* __restrict__ ci,
                float* __restrict__ out, int n)
{
    __shared__ u64 scp[64];                       // packed (cr, ci)
    int tid = threadIdx.x;
    if (tid < 64) scp[tid] = pack2(__ldg(cr + tid), __ldg(ci + tid));
    __syncthreads();

    int npairs  = (n + OPT - 1) / OPT;
    int stride  = GRID * TPB;                     // threads in the persistent grid

#pragma unroll 1
    for (int pair = blockIdx.x * TPB + tid; pair < npairs; pair += stride) {
        int base = pair * OPT;                    // outputs [base, base+2)
        int m0 = base - 5;                        // halo: base-5 .. base+3, t in [0,8]

        u64 r2p[9];                               // (s, s) duplicated, s = |x|^2
        u64 abp[9];                               // (a, -b); only t in [2,6] used
        bool interior = (m0 >= 0) && (base + 4 <= n);
#pragma unroll
        for (int t = 0; t < 9; t++) {
            float a, b;
            if (interior) {
                a = __ldg(xr + m0 + t);
                b = __ldg(xi + m0 + t);
            } else {
                int m = m0 + t;
                bool ok = (m >= 0) && (m < n);
                a = ok ? __ldg(xr + m) : 0.0f;
                b = ok ? __ldg(xi + m) : 0.0f;
            }
            float s = fmaf(a, a, b * b);
            r2p[t] = pack2(s, s);
            if (t >= 2 && t <= 6) abp[t] = pack2(a, -b);
        }

        u64 yp[OPT];                              // packed (a*wr | -b*wi) accum
        yp[0] = pack2(0.0f, 0.0f);
        yp[1] = yp[0];

        // d-outer: each packed coeff loaded once (uniform LDS -> broadcast).
#pragma unroll
        for (int d = 0; d < 4; d++) {
            u64 wp[OPT];
            u64 c0 = scp[d];                      // order-1 main term
            wp[0] = c0; wp[1] = c0;

            // Horner triple for (d, OFF): wp += s*(c2 + s*(c4 + s*c6))
#define HACC(C2, C4, C6, OFF) {                                                    \
            u64 c6v = scp[(C6)], c4v = scp[(C4)], c2v = scp[(C2)];                  \
            _Pragma("unroll")                                                       \
            for (int q = 0; q < OPT; q++) {                                         \
                u64 s = r2p[q - d + 5 + (OFF)];                                     \
                u64 p = fma2(s, c6v, c4v);                                          \
                p     = fma2(s, p,   c2v);                                          \
                wp[q] = fma2(s, p, wp[q]);                                          \
            } }

            HACC( 4 + d,  8 + d, 12 + d,  0)      // main
            HACC(16 + d, 24 + d, 32 + d, -1)      // lag 1
            HACC(20 + d, 28 + d, 36 + d, -2)      // lag 2
            HACC(40 + d, 48 + d, 56 + d,  1)      // lead 1
            HACC(44 + d, 52 + d, 60 + d,  2)      // lead 2
#undef HACC

            // yp += (a, -b) * (wr, wi)
#pragma unroll
            for (int q = 0; q < OPT; q++)
                yp[q] = fma2(abp[q - d + 5], wp[q], yp[q]);
        }

        // Horizontal add: Re(y) = a*wr_sum + (-b)*wi_sum.
#pragma unroll
        for (int q = 0; q < OPT; q++) {
            int g = base + q;
            if (g < n) {
                float lo, hi;
                unpack2(yp[q], lo, hi);
                out[g] = lo + hi;
            }
        }
    }
}

extern "C" void kernel_launch(void* const* d_in, const int* in_sizes, int n_in,
                              void* d_out, int out_size)
{
    // Confirmed layout: d_in = {x_real[N], x_imag[N], coeffs_real[64],
    // coeffs_imag[64]}, all float32; out = float32[N] (real part only).
    const float* xr = (const float*)d_in[0];
    const float* xi = (const float*)d_in[1];
    const float* cr = (const float*)d_in[2];
    const float* ci = (const float*)d_in[3];

    int n = in_sizes[0];
    if (n > out_size) n = out_size;               // never write past d_out

    dpd_kernel<<<GRID, TPB>>>(xr, xi, cr, ci, (float*)d_out, n);
}

// round 14
// speedup vs baseline: 1.3434x; 1.3434x over previous
#include <cuda_runtime.h>

#define TPB  256
#define OPT  4                  // outputs per thread
#define CPS  4                  // CTAs/SM pinned: 64-reg cap, occ ~50%, single wave

typedef unsigned long long u64;

// ---- packed f32x2 helpers (sm_103a FFMA2 path, PTX-only) ----
__device__ __forceinline__ u64 pack2(float lo, float hi) {
    u64 r; asm("mov.b64 %0, {%1, %2};" : "=l"(r) : "f"(lo), "f"(hi)); return r;
}
__device__ __forceinline__ void unpack2(u64 v, float& lo, float& hi) {
    asm("mov.b64 {%0, %1}, %2;" : "=f"(lo), "=f"(hi) : "l"(v));
}
__device__ __forceinline__ u64 fma2(u64 a, u64 b, u64 c) {
    u64 d; asm("fma.rn.f32x2 %0, %1, %2, %3;" : "=l"(d) : "l"(a), "l"(b), "l"(c)); return d;
}

// GMP DPD, real-part output (harness drops imag):
//   Re(y[n]) = sum_{d=0..3} ( a[n-d]*wr_d(n) - b[n-d]*wi_d(n) )
//   w_d(n)   = c(1,d) + sum_{off=-2..2} P_{d,off}(s[n-d+off]),  s = |x|^2
//   P(s)     = s*(c2 + s*(c4 + s*c6))     (Horner; kills r4/r6 register arrays)
// x zero-padded outside [0,N) (matches reference delay/lag/lead concats).
//
// Coefficient column order (reference basis):
//   [0:16)  main : order {1,3,5,7} x delay {0..3}
//   [16:40) lag  : order {3,5,7} x lag  {1,2} x delay {0..3}
//   [40:64) lead : order {3,5,7} x lead {1,2} x delay {0..3}
// (c2,c4,c6) triples per (d, off):
//   off= 0: ( 4+d,  8+d, 12+d)   off=-1: (16+d, 24+d, 32+d)
//   off=-2: (20+d, 28+d, 36+d)   off=+1: (40+d, 48+d, 56+d)
//   off=+2: (44+d, 52+d, 60+d)
__global__ __launch_bounds__(TPB, CPS)
void dpd_kernel(const float* __restrict__ xr, const float* __restrict__ xi,
                const float* __restrict__ cr, const float* __restrict__ ci,
                float* __restrict__ out, int n)
{
    __shared__ u64 scp[64];                       // packed (cr, ci)
    int tid = threadIdx.x;
    if (tid < 64) scp[tid] = pack2(__ldg(cr + tid), __ldg(ci + tid));
    __syncthreads();

    int base = (blockIdx.x * TPB + tid) * OPT;    // outputs [base, base+OPT)
    if (base >= n) return;

    // Halo: global positions base-5 .. base+5 -> local t in [0,10].
    u64 r2p[11];                                  // (s, s) duplicated, s = |x|^2
    u64 abp[9];                                   // (a, -b); t in [2,8] used
    int m0 = base - 5;
    bool interior = (m0 >= 0) && (base + 6 <= n);
#pragma unroll
    for (int t = 0; t < 11; t++) {
        float a, b;
        if (interior) {
            a = __ldg(xr + m0 + t);
            b = __ldg(xi + m0 + t);
        } else {
            int m = m0 + t;
            bool ok = (m >= 0) && (m < n);
            a = ok ? __ldg(xr + m) : 0.0f;
            b = ok ? __ldg(xi + m) : 0.0f;
        }
        float s = fmaf(a, a, b * b);
        r2p[t] = pack2(s, s);
        if (t >= 2 && t <= 8) abp[t] = pack2(a, -b);
    }

    u64 yp[OPT];                                  // packed (a*wr | -b*wi) accum
    u64 z = pack2(0.0f, 0.0f);
#pragma unroll
    for (int q = 0; q < OPT; q++) yp[q] = z;

    // d-outer: each packed coeff loaded once (uniform LDS -> broadcast).
#pragma unroll
    for (int d = 0; d < 4; d++) {
        u64 wp[OPT];
        u64 c0 = scp[d];                          // order-1 main term
#pragma unroll
        for (int q = 0; q < OPT; q++) wp[q] = c0;

        // Horner triple for (d, OFF): wp += s*(c2 + s*(c4 + s*c6))
#define HACC(C2, C4, C6, OFF) {                                                    \
        u64 c6v = scp[(C6)], c4v = scp[(C4)], c2v = scp[(C2)];                      \
        _Pragma("unroll")                                                           \
        for (int q = 0; q < OPT; q++) {                                             \
            u64 s = r2p[q - d + 5 + (OFF)];                                         \
            u64 p = fma2(s, c6v, c4v);                                              \
            p     = fma2(s, p,   c2v);                                              \
            wp[q] = fma2(s, p, wp[q]);                                              \
        } }

        HACC( 4 + d,  8 + d, 12 + d,  0)          // main
        HACC(16 + d, 24 + d, 32 + d, -1)          // lag 1
        HACC(20 + d, 28 + d, 36 + d, -2)          // lag 2
        HACC(40 + d, 48 + d, 56 + d,  1)          // lead 1
        HACC(44 + d, 52 + d, 60 + d,  2)          // lead 2
#undef HACC

        // yp += (a, -b) * (wr, wi)   [lanes: a*wr | -b*wi]
#pragma unroll
        for (int q = 0; q < OPT; q++)
            yp[q] = fma2(abp[q - d + 5], wp[q], yp[q]);
    }

    // Horizontal add per output: Re(y) = a*wr_sum + (-b)*wi_sum.
#pragma unroll
    for (int q = 0; q < OPT; q++) {
        int g = base + q;
        if (g < n) {
            float lo, hi;
            unpack2(yp[q], lo, hi);
            out[g] = lo + hi;
        }
    }
}

extern "C" void kernel_launch(void* const* d_in, const int* in_sizes, int n_in,
                              void* d_out, int out_size)
{
    // Confirmed layout: d_in = {x_real[N], x_imag[N], coeffs_real[64],
    // coeffs_imag[64]}, all float32; out = float32[N] (real part only).
    const float* xr = (const float*)d_in[0];
    const float* xi = (const float*)d_in[1];
    const float* cr = (const float*)d_in[2];
    const float* ci = (const float*)d_in[3];

    int n = in_sizes[0];
    if (n > out_size) n = out_size;               // never write past d_out

    int threads = (n + OPT - 1) / OPT;
    int blocks  = (threads + TPB - 1) / TPB;      // 512 blocks @ N=524288: 1 wave
    dpd_kernel<<<blocks, TPB>>>(xr, xi, cr, ci, (float*)d_out, n);
}